// round 5
// baseline (speedup 1.0000x reference)
#include <cuda_runtime.h>
#include <math_constants.h>

// VQ-VAE vector quantizer. Bitwise-emulates the reference fp32 pipeline:
//   d_k = fl32( fl32(A - 2*M_k) + B_k )
//   A   = sum(x^2)  (float2 leaves + binary tree)   [frozen order]
//   M_k = x . e_k   (sequential ascending-d fp32 FMA chain from 0) [frozen]
//   B_k = sum(e^2)  (sequential ascending chain)    [frozen]
//   argmin, tie -> lowest index.
//
// R5: double-buffered E staging with register prefetch (LDG issued before
// compute, STS after -> latency hidden, 1 sync/chunk); TP=128 as two halves
// sharing each staged chunk (staging cost per dot halved). Code-paired f32x2
// lanes as R4. 2 blocks/SM, grid 512.

#define K_CODES   1024
#define D_DIM     64
#define TP        128     // positions per block (two halves of 64)
#define TK        128     // codes per chunk
#define EROW      132     // Es row stride in floats (16B-aligned)
#define EBUF      (64 * EROW)   // 8448 floats per buffer
#define ENC_OFF   4194304
#define LOSS_OFF  4259840
#define NLL_OFF   4259841
#define TOTAL_OUT 4259842

typedef unsigned long long ull;

__device__ double g_loss_acc;
__device__ int    g_done;
__device__ float  g_eB[K_CODES];   // fp32 ||e_k||^2, sequential chain

// ---- packed f32x2 helpers (sm_100+); each lane rounds like scalar op ----
__device__ __forceinline__ ull pk2(float a, float b) {
    ull r; asm("mov.b64 %0, {%1, %2};" : "=l"(r) : "f"(a), "f"(b)); return r;
}
__device__ __forceinline__ void upk2(ull v, float& a, float& b) {
    asm("mov.b64 {%0, %1}, %2;" : "=f"(a), "=f"(b) : "l"(v));
}
__device__ __forceinline__ ull ffma2(ull a, ull b, ull c) {
    ull r; asm("fma.rn.f32x2 %0, %1, %2, %3;" : "=l"(r) : "l"(a), "l"(b), "l"(c)); return r;
}
__device__ __forceinline__ ull add2(ull a, ull b) {
    ull r; asm("add.rn.f32x2 %0, %1, %2;" : "=l"(r) : "l"(a), "l"(b)); return r;
}

// Kernel 0: B_k chains + zero loss accumulator.
__global__ void __launch_bounds__(256) vq_prep(const float* __restrict__ emb) {
    int k = blockIdx.x * blockDim.x + threadIdx.x;
    if (k == 0) g_loss_acc = 0.0;
    if (k < K_CODES) {
        const float* row = emb + (size_t)k * D_DIM;
        float b = 0.0f;
        #pragma unroll
        for (int i = 0; i < 16; i++) {
            float4 v = *(const float4*)(row + i * 4);
            b = __fmaf_rn(v.x, v.x, b);
            b = __fmaf_rn(v.y, v.y, b);
            b = __fmaf_rn(v.z, v.z, b);
            b = __fmaf_rn(v.w, v.w, b);
        }
        g_eB[k] = b;
    }
}

// Main kernel: one block = 128 positions of one image, all 1024 codes.
__global__ void __launch_bounds__(256, 2) vq_main(const float* __restrict__ x,
                                                  const float* __restrict__ emb,
                                                  float* __restrict__ out,
                                                  int out_size, int nblocks) {
    extern __shared__ char smem_raw[];
    float* Xs   = (float*)smem_raw;                        // [64][128]     32768 B
    float* Es   = (float*)(smem_raw + 32768);              // [2][64][132]  67584 B
    float* Bs   = (float*)(smem_raw + 32768 + 67584);      // [2][128]       1024 B
    float* As   = (float*)(smem_raw + 101376);             // [128]           512 B
    int*   idx_s = (int*)(smem_raw + 101888);              // [128]           512 B
    // reduction overlays Es buffer 0 (only used after all chunks done):
    float* rV = Es;                                        // [16][128]
    int*   rI = (int*)Es + 2048;                           // [16][128]

    const int tid = threadIdx.x;
    const int tx = tid & 15;            // position group (4 per half)
    const int ty = tid >> 4;            // code group (8 codes)
    const int b  = blockIdx.x >> 3;
    const int p0 = (blockIdx.x & 7) * TP;
    const int st_dc = tid & 15;         // staging d-chunk (float4)
    const int st_s  = st_dc >> 1;       // staging swizzle const
    const int krow  = tid >> 4;

    // ---- load X tile: Xs[d][pp] = x[(b*64+d)*1024 + p0 + pp] ----
    {
        const float* xb = x + (size_t)b * 65536 + p0;
        int chunk = tid & 31;           // 32 float4 per row of 128
        int r0    = tid >> 5;           // 8 rows per iter
        #pragma unroll
        for (int it = 0; it < 8; it++) {
            int d = r0 + it * 8;
            float4 v = *(const float4*)(xb + d * 1024 + chunk * 4);
            *(float4*)&Xs[d * TP + chunk * 4] = v;
        }
    }

    // ---- stage chunk 0 E (transposed + granule-XOR swizzle) + Bs0 ----
    //   element (d, k) -> word  d*EROW + (((k>>2) ^ (d>>3)) << 2) + (k&3)
    {
        #pragma unroll
        for (int it = 0; it < 8; it++) {
            int k = krow + it * 16;
            float4 v = *(const float4*)(emb + (size_t)k * 64 + st_dc * 4);
            int swc = ((((k >> 2) ^ st_s) << 2) + (k & 3));
            Es[(st_dc * 4 + 0) * EROW + swc] = v.x;
            Es[(st_dc * 4 + 1) * EROW + swc] = v.y;
            Es[(st_dc * 4 + 2) * EROW + swc] = v.z;
            Es[(st_dc * 4 + 3) * EROW + swc] = v.w;
        }
        if (tid < TK) Bs[tid] = g_eB[tid];
    }
    __syncthreads();

    // ---- A_p = sum(x^2): float2 leaves + binary tree (frozen order) ----
    if (tid < TP) {
        float l[32];
        #pragma unroll
        for (int t = 0; t < 32; t++) {
            float a = Xs[(2 * t) * TP + tid];
            float c = Xs[(2 * t + 1) * TP + tid];
            l[t] = __fmaf_rn(c, c, __fmul_rn(a, a));
        }
        #pragma unroll
        for (int off = 16; off >= 1; off >>= 1)
            #pragma unroll
            for (int t = 0; t < 16; t++)
                if (t < off) l[t] = __fadd_rn(l[t], l[t + off]);
        As[tid] = l[0];
    }
    __syncthreads();

    const ull neg2 = pk2(-2.0f, -2.0f);
    float bv[2][4];
    int   bi[2][4];
    #pragma unroll
    for (int h = 0; h < 2; h++)
        #pragma unroll
        for (int i = 0; i < 4; i++) { bv[h][i] = CUDART_INF_F; bi[h][i] = 0; }

    // ---- K chunks, software-pipelined E staging ----
    float4 ev[8];
    float  bsv = 0.0f;
    for (int kc = 0; kc < K_CODES / TK; kc++) {
        const int   k0  = kc * TK;
        const float* Ecur = Es + (kc & 1) * EBUF;
        const float* Bcur = Bs + (kc & 1) * TK;

        // prefetch next chunk into registers (latency hidden by compute)
        if (kc < 7) {
            const int k0n = k0 + TK;
            #pragma unroll
            for (int it = 0; it < 8; it++) {
                int k = krow + it * 16;
                ev[it] = *(const float4*)(emb + (size_t)(k0n + k) * 64 + st_dc * 4);
            }
            if (tid < TK) bsv = g_eB[k0n + tid];
        }

        // compute both halves on current buffer
        #pragma unroll
        for (int h = 0; h < 2; h++) {
            ull acc[4][4];
            #pragma unroll
            for (int p = 0; p < 4; p++)
                #pragma unroll
                for (int kk = 0; kk < 4; kk++) acc[p][kk] = 0ull;

            #pragma unroll
            for (int d8 = 0; d8 < 8; d8++) {
                const int ga = (2 * ty)     ^ d8;
                const int gb = (2 * ty + 1) ^ d8;
                #pragma unroll
                for (int j = 0; j < 8; j++) {
                    const int d = d8 * 8 + j;
                    float4 xv = *(const float4*)&Xs[d * TP + h * 64 + tx * 4];
                    ulonglong2 e01 = *(const ulonglong2*)&Ecur[d * EROW + ga * 4];
                    ulonglong2 e23 = *(const ulonglong2*)&Ecur[d * EROW + gb * 4];
                    ull ep[4] = { e01.x, e01.y, e23.x, e23.y };
                    float xs4[4] = { xv.x, xv.y, xv.z, xv.w };
                    #pragma unroll
                    for (int p = 0; p < 4; p++) {
                        ull xp = pk2(xs4[p], xs4[p]);
                        #pragma unroll
                        for (int kk = 0; kk < 4; kk++)
                            acc[p][kk] = ffma2(xp, ep[kk], acc[p][kk]);
                    }
                }
            }

            // fold: d = fl(fl(A - 2M) + B); even code first -> lowest idx on tie
            #pragma unroll
            for (int p = 0; p < 4; p++) {
                float Ap = As[h * 64 + tx * 4 + p];
                ull Apk = pk2(Ap, Ap);
                #pragma unroll
                for (int kk = 0; kk < 4; kk++) {
                    ull B2 = ((const ull*)Bcur)[ty * 4 + kk];
                    ull dpk = add2(ffma2(neg2, acc[p][kk], Apk), B2);
                    float d0, d1;
                    upk2(dpk, d0, d1);
                    int ke = k0 + ty * 8 + 2 * kk;
                    if (d0 < bv[h][p]) { bv[h][p] = d0; bi[h][p] = ke; }
                    if (d1 < bv[h][p]) { bv[h][p] = d1; bi[h][p] = ke + 1; }
                }
            }
        }

        // store prefetched chunk into the other buffer
        if (kc < 7) {
            float* Enxt = Es + ((kc + 1) & 1) * EBUF;
            #pragma unroll
            for (int it = 0; it < 8; it++) {
                int k = krow + it * 16;
                int swc = ((((k >> 2) ^ st_s) << 2) + (k & 3));
                Enxt[(st_dc * 4 + 0) * EROW + swc] = ev[it].x;
                Enxt[(st_dc * 4 + 1) * EROW + swc] = ev[it].y;
                Enxt[(st_dc * 4 + 2) * EROW + swc] = ev[it].z;
                Enxt[(st_dc * 4 + 3) * EROW + swc] = ev[it].w;
            }
            if (tid < TK) Bs[((kc + 1) & 1) * TK + tid] = bsv;
        }
        __syncthreads();
    }

    // ---- cross-thread (ty) reduction per position: min, tie -> lowest idx ----
    #pragma unroll
    for (int h = 0; h < 2; h++)
        #pragma unroll
        for (int p = 0; p < 4; p++) {
            int pos = h * 64 + tx * 4 + p;
            rV[ty * TP + pos] = bv[h][p];
            rI[ty * TP + pos] = bi[h][p];
        }
    __syncthreads();
    if (tid < TP) {
        float best = rV[tid];
        int besti  = rI[tid];
        #pragma unroll
        for (int t = 1; t < 16; t++) {
            float v = rV[t * TP + tid];
            int iv  = rI[t * TP + tid];
            if (v < best || (v == best && iv < besti)) { best = v; besti = iv; }
        }
        idx_s[tid] = besti;
        if (out_size >= TOTAL_OUT)
            out[ENC_OFF + b * 1024 + p0 + tid] = (float)besti;
    }
    __syncthreads();

    // ---- output (straight-through: x + fl(q - x)) + loss partial ----
    float lsum = 0.0f;
    #pragma unroll
    for (int j = 0; j < 32; j++) {
        int i  = tid + j * 256;
        int pp = i & 127;
        int d  = i >> 7;
        float q  = emb[(size_t)idx_s[pp] * 64 + d];
        float xv = Xs[d * TP + pp];
        float df = __fadd_rn(q, -xv);
        lsum += df * df;
        out[((size_t)b * 64 + d) * 1024 + p0 + pp] = __fadd_rn(xv, df);
    }
    #pragma unroll
    for (int off = 16; off > 0; off >>= 1)
        lsum += __shfl_down_sync(0xffffffffu, lsum, off);
    __shared__ float wsum[8];
    if ((tid & 31) == 0) wsum[tid >> 5] = lsum;
    __syncthreads();
    if (tid == 0) {
        float t = 0.0f;
        #pragma unroll
        for (int w = 0; w < 8; w++) t += wsum[w];
        atomicAdd(&g_loss_acc, (double)t);
        __threadfence();
        int old = atomicAdd(&g_done, 1);
        if (old == nblocks - 1) {               // last block finalizes
            g_done = 0;
            if (out_size >= TOTAL_OUT) {
                float m = (float)(g_loss_acc * (1.0 / 4194304.0));
                out[LOSS_OFF] = __fadd_rn(m, __fmul_rn(0.25f, m));
                out[NLL_OFF]  = 1.0f;
            }
        }
    }
}

extern "C" void kernel_launch(void* const* d_in, const int* in_sizes, int n_in,
                              void* d_out, int out_size) {
    const float* x   = (const float*)d_in[0];
    const float* emb = (const float*)d_in[1];
    if (n_in >= 2 && in_sizes[0] == K_CODES * D_DIM) {
        const float* t = x; x = emb; emb = t;
    }
    float* out = (float*)d_out;

    const int smem_bytes = 32768 + 67584 + 1024 + 512 + 512;   // 102400
    cudaFuncSetAttribute(vq_main, cudaFuncAttributeMaxDynamicSharedMemorySize,
                         smem_bytes);

    vq_prep<<<4, 256>>>(emb);
    vq_main<<<512, 256, smem_bytes>>>(x, emb, out, out_size, 512);
}

// round 6
// speedup vs baseline: 2.6470x; 2.6470x over previous
#include <cuda_runtime.h>
#include <math_constants.h>

// VQ-VAE vector quantizer. Bitwise-emulates the reference fp32 pipeline:
//   d_k = fl32( fl32(A - 2*M_k) + B_k )
//   A   = sum(x^2)  (float2 leaves + binary tree)   [frozen order]
//   M_k = x . e_k   (sequential ascending-d fp32 FMA chain from 0) [frozen]
//   B_k = sum(e^2)  (sequential ascending chain)    [frozen]
//   argmin, tie -> lowest index.
//
// R6: pair-interleaved E smem layout ({e_2p, e_2p+1} contiguous per d) ->
// packed e operand is ONE broadcast LDS.64, d-step overhead 9 slots/16 FFMA2.
// Double-buffered staging with one sync per chunk, synchronous order, ZERO
// persistent prefetch registers (R5's spill bug class eliminated).

#define K_CODES   1024
#define D_DIM     64
#define TP        64      // positions per block
#define TK        128     // codes per chunk (64 pairs)
#define PSTRIDE   138     // floats per pair-row (64 d * 2 + 10 pad, even)
#define EBUF      (64 * PSTRIDE)
#define ENC_OFF   4194304
#define LOSS_OFF  4259840
#define NLL_OFF   4259841
#define TOTAL_OUT 4259842

typedef unsigned long long ull;

__device__ double g_loss_acc;
__device__ int    g_done;
__device__ float  g_eB[K_CODES];   // fp32 ||e_k||^2, sequential chain

// ---- packed f32x2 helpers (sm_100+); each lane rounds like scalar op ----
__device__ __forceinline__ ull pk2(float a, float b) {
    ull r; asm("mov.b64 %0, {%1, %2};" : "=l"(r) : "f"(a), "f"(b)); return r;
}
__device__ __forceinline__ void upk2(ull v, float& a, float& b) {
    asm("mov.b64 {%0, %1}, %2;" : "=f"(a), "=f"(b) : "l"(v));
}
__device__ __forceinline__ ull ffma2(ull a, ull b, ull c) {
    ull r; asm("fma.rn.f32x2 %0, %1, %2, %3;" : "=l"(r) : "l"(a), "l"(b), "l"(c)); return r;
}
__device__ __forceinline__ ull add2(ull a, ull b) {
    ull r; asm("add.rn.f32x2 %0, %1, %2;" : "=l"(r) : "l"(a), "l"(b)); return r;
}

// Kernel 0: B_k chains + zero loss accumulator.
__global__ void __launch_bounds__(256) vq_prep(const float* __restrict__ emb) {
    int k = blockIdx.x * blockDim.x + threadIdx.x;
    if (k == 0) g_loss_acc = 0.0;
    if (k < K_CODES) {
        const float* row = emb + (size_t)k * D_DIM;
        float b = 0.0f;
        #pragma unroll
        for (int i = 0; i < 16; i++) {
            float4 v = *(const float4*)(row + i * 4);
            b = __fmaf_rn(v.x, v.x, b);
            b = __fmaf_rn(v.y, v.y, b);
            b = __fmaf_rn(v.z, v.z, b);
            b = __fmaf_rn(v.w, v.w, b);
        }
        g_eB[k] = b;
    }
}

// Main kernel: one block = 64 positions of one image, all 1024 codes.
__global__ void __launch_bounds__(256, 2) vq_main(const float* __restrict__ x,
                                                  const float* __restrict__ emb,
                                                  float* __restrict__ out,
                                                  int out_size, int nblocks) {
    extern __shared__ char smem_raw[];
    float* Xs   = (float*)smem_raw;                        // [64][64]        16384 B
    float* Es   = (float*)(smem_raw + 16384);              // [2][64][138]    70656 B
    float* Bs   = (float*)(smem_raw + 16384 + 70656);      // [2][128]         1024 B
    float* As   = (float*)(smem_raw + 88064);              // [64]              256 B
    int*   idx_s = (int*)(smem_raw + 88320);               // [64]              256 B
    // reduction overlays Es buffer 0 (only used after all chunks done):
    float* rV = Es;                                        // [16][64]
    int*   rI = (int*)Es + 1024;                           // [16][64]

    const int tid = threadIdx.x;
    const int tx = tid & 15;            // position group (4 positions)
    const int ty = tid >> 4;            // code group (8 codes = 4 pairs)
    const int b  = blockIdx.x >> 4;
    const int p0 = (blockIdx.x & 15) * TP;
    const int pr = tid >> 2;            // staging pair-row 0..63
    const int q  = tid & 3;             // staging d-quarter (16 d each)

    // ---- load X tile: Xs[d][pp] = x[(b*64+d)*1024 + p0 + pp] ----
    {
        const float* xb = x + (size_t)b * 65536 + p0;
        int chunk = tid & 15;           // 16 float4 per row of 64
        int r0    = tid >> 4;           // 16 rows per iter
        #pragma unroll
        for (int it = 0; it < 4; it++) {
            int d = r0 + it * 16;
            float4 v = *(const float4*)(xb + d * 1024 + chunk * 4);
            *(float4*)&Xs[d * TP + chunk * 4] = v;
        }
    }
    __syncthreads();

    // ---- A_p = sum(x^2): float2 leaves + binary tree (frozen order) ----
    if (tid < TP) {
        float l[32];
        #pragma unroll
        for (int t = 0; t < 32; t++) {
            float a = Xs[(2 * t) * TP + tid];
            float c = Xs[(2 * t + 1) * TP + tid];
            l[t] = __fmaf_rn(c, c, __fmul_rn(a, a));
        }
        #pragma unroll
        for (int off = 16; off >= 1; off >>= 1)
            #pragma unroll
            for (int t = 0; t < 16; t++)
                if (t < off) l[t] = __fadd_rn(l[t], l[t + off]);
        As[tid] = l[0];
    }
    __syncthreads();

    // per-thread packed A pairs would change rounding? No: fold still scalar-
    // equivalent; keep Apk built per chunk from As (cheap).
    const ull neg2 = pk2(-2.0f, -2.0f);
    float bv[4];
    int   bi[4];
    #pragma unroll
    for (int i = 0; i < 4; i++) { bv[i] = CUDART_INF_F; bi[i] = 0; }

    // ---- K chunks: stage(c) -> sync -> compute(c); double buffer makes the
    //      single sync safe (stage(c) only races compute(c-1) on other buf) --
    for (int kc = 0; kc < K_CODES / TK; kc++) {
        const int k0 = kc * TK;
        float* Eb = Es + (kc & 1) * EBUF;
        float* Bb = Bs + (kc & 1) * TK;

        // stage: pair-row pr gets codes {k0+2pr, k0+2pr+1}, d in [q*16, q*16+16)
        {
            const float* r0 = emb + (size_t)(k0 + 2 * pr) * 64 + q * 16;
            float* dst = Eb + pr * PSTRIDE + q * 32;
            #pragma unroll
            for (int i = 0; i < 4; i++) {
                float4 lo = *(const float4*)(r0 + i * 4);
                float4 hi = *(const float4*)(r0 + 64 + i * 4);
                float2* d2 = (float2*)(dst + i * 8);
                d2[0] = make_float2(lo.x, hi.x);
                d2[1] = make_float2(lo.y, hi.y);
                d2[2] = make_float2(lo.z, hi.z);
                d2[3] = make_float2(lo.w, hi.w);
            }
            if (tid < TK) Bb[tid] = g_eB[k0 + tid];
        }
        __syncthreads();

        // compute: acc[4 pos][4 pairs], sequential ascending-d chains
        ull acc[4][4];
        #pragma unroll
        for (int p = 0; p < 4; p++)
            #pragma unroll
            for (int kk = 0; kk < 4; kk++) acc[p][kk] = 0ull;

        const float* Er = Eb + ty * 4 * PSTRIDE;
        #pragma unroll
        for (int d = 0; d < 64; d++) {
            float4 xv = *(const float4*)&Xs[d * TP + tx * 4];
            ull e0 = *(const ull*)&Er[0 * PSTRIDE + 2 * d];
            ull e1 = *(const ull*)&Er[1 * PSTRIDE + 2 * d];
            ull e2 = *(const ull*)&Er[2 * PSTRIDE + 2 * d];
            ull e3 = *(const ull*)&Er[3 * PSTRIDE + 2 * d];
            float xs4[4] = { xv.x, xv.y, xv.z, xv.w };
            #pragma unroll
            for (int p = 0; p < 4; p++) {
                ull xp = pk2(xs4[p], xs4[p]);
                acc[p][0] = ffma2(xp, e0, acc[p][0]);
                acc[p][1] = ffma2(xp, e1, acc[p][1]);
                acc[p][2] = ffma2(xp, e2, acc[p][2]);
                acc[p][3] = ffma2(xp, e3, acc[p][3]);
            }
        }

        // fold: d = fl(fl(A - 2M) + B); even code first -> lowest idx on tie
        #pragma unroll
        for (int p = 0; p < 4; p++) {
            float Ap = As[tx * 4 + p];
            ull Apk = pk2(Ap, Ap);
            #pragma unroll
            for (int kk = 0; kk < 4; kk++) {
                ull B2 = ((const ull*)Bb)[ty * 4 + kk];
                ull dpk = add2(ffma2(neg2, acc[p][kk], Apk), B2);
                float d0, d1;
                upk2(dpk, d0, d1);
                int ke = k0 + ty * 8 + 2 * kk;
                if (d0 < bv[p]) { bv[p] = d0; bi[p] = ke; }
                if (d1 < bv[p]) { bv[p] = d1; bi[p] = ke + 1; }
            }
        }
    }

    // ---- cross-thread (ty) reduction per position: min, tie -> lowest idx ----
    __syncthreads();   // all compute done before overlaying Es
    #pragma unroll
    for (int p = 0; p < 4; p++) {
        rV[ty * TP + tx * 4 + p] = bv[p];
        rI[ty * TP + tx * 4 + p] = bi[p];
    }
    __syncthreads();
    if (tid < TP) {
        float best = rV[tid];
        int besti  = rI[tid];
        #pragma unroll
        for (int t = 1; t < 16; t++) {
            float v = rV[t * TP + tid];
            int iv  = rI[t * TP + tid];
            if (v < best || (v == best && iv < besti)) { best = v; besti = iv; }
        }
        idx_s[tid] = besti;
        if (out_size >= TOTAL_OUT)
            out[ENC_OFF + b * 1024 + p0 + tid] = (float)besti;
    }
    __syncthreads();

    // ---- output (straight-through: x + fl(q - x)) + loss partial ----
    float lsum = 0.0f;
    #pragma unroll
    for (int j = 0; j < 16; j++) {
        int i  = tid + j * 256;
        int pp = i & 63;
        int d  = i >> 6;
        float q2 = emb[(size_t)idx_s[pp] * 64 + d];
        float xv = Xs[d * TP + pp];
        float df = __fadd_rn(q2, -xv);
        lsum += df * df;
        out[((size_t)b * 64 + d) * 1024 + p0 + pp] = __fadd_rn(xv, df);
    }
    #pragma unroll
    for (int off = 16; off > 0; off >>= 1)
        lsum += __shfl_down_sync(0xffffffffu, lsum, off);
    __shared__ float wsum[8];
    if ((tid & 31) == 0) wsum[tid >> 5] = lsum;
    __syncthreads();
    if (tid == 0) {
        float t = 0.0f;
        #pragma unroll
        for (int w = 0; w < 8; w++) t += wsum[w];
        atomicAdd(&g_loss_acc, (double)t);
        __threadfence();
        int old = atomicAdd(&g_done, 1);
        if (old == nblocks - 1) {               // last block finalizes
            g_done = 0;
            if (out_size >= TOTAL_OUT) {
                float m = (float)(g_loss_acc * (1.0 / 4194304.0));
                out[LOSS_OFF] = __fadd_rn(m, __fmul_rn(0.25f, m));
                out[NLL_OFF]  = 1.0f;
            }
        }
    }
}

extern "C" void kernel_launch(void* const* d_in, const int* in_sizes, int n_in,
                              void* d_out, int out_size) {
    const float* x   = (const float*)d_in[0];
    const float* emb = (const float*)d_in[1];
    if (n_in >= 2 && in_sizes[0] == K_CODES * D_DIM) {
        const float* t = x; x = emb; emb = t;
    }
    float* out = (float*)d_out;

    const int smem_bytes = 16384 + 70656 + 1024 + 256 + 256;   // 88576
    cudaFuncSetAttribute(vq_main, cudaFuncAttributeMaxDynamicSharedMemorySize,
                         smem_bytes);

    vq_prep<<<4, 256>>>(emb);
    vq_main<<<1024, 256, smem_bytes>>>(x, emb, out, out_size, 1024);
}

// round 7
// speedup vs baseline: 3.0387x; 1.1480x over previous
#include <cuda_runtime.h>
#include <math_constants.h>

// VQ-VAE vector quantizer. Bitwise-emulates the reference fp32 pipeline:
//   d_k = fl32( fl32(A - 2*M_k) + B_k )
//   A   = sum(x^2)  (float2 leaves + binary tree)   [frozen order]
//   M_k = x . e_k   (sequential ascending-d fp32 FMA chain from 0) [frozen]
//   B_k = sum(e^2)  (sequential ascending chain)    [frozen]
//   argmin, tie -> lowest index.
//
// R7: warp-uniform code mapping (ty = tid>>5 constant per warp) + thread tile
// 4 pos x 16 codes -> e-loads are 4 broadcast LDS.128 per d-step; LDS instrs
// per FFMA2 cut 2.6x vs R4. Granule-XOR E layout (R4) double-buffered with
// ONE sync per chunk, zero persistent prefetch regs. TP=128, grid 512.

#define K_CODES   1024
#define D_DIM     64
#define TP        128     // positions per block
#define TK        128     // codes per chunk
#define EROW      132     // E row stride in floats (16B-aligned)
#define EBUF      (64 * EROW)
#define ENC_OFF   4194304
#define LOSS_OFF  4259840
#define NLL_OFF   4259841
#define TOTAL_OUT 4259842

typedef unsigned long long ull;

__device__ double g_loss_acc;
__device__ int    g_done;
__device__ float  g_eB[K_CODES];   // fp32 ||e_k||^2, sequential chain

// ---- packed f32x2 helpers (sm_100+); each lane rounds like scalar op ----
__device__ __forceinline__ ull pk2(float a, float b) {
    ull r; asm("mov.b64 %0, {%1, %2};" : "=l"(r) : "f"(a), "f"(b)); return r;
}
__device__ __forceinline__ void upk2(ull v, float& a, float& b) {
    asm("mov.b64 {%0, %1}, %2;" : "=f"(a), "=f"(b) : "l"(v));
}
__device__ __forceinline__ ull ffma2(ull a, ull b, ull c) {
    ull r; asm("fma.rn.f32x2 %0, %1, %2, %3;" : "=l"(r) : "l"(a), "l"(b), "l"(c)); return r;
}
__device__ __forceinline__ ull add2(ull a, ull b) {
    ull r; asm("add.rn.f32x2 %0, %1, %2;" : "=l"(r) : "l"(a), "l"(b)); return r;
}

// Kernel 0: B_k chains + zero loss accumulator.
__global__ void __launch_bounds__(256) vq_prep(const float* __restrict__ emb) {
    int k = blockIdx.x * blockDim.x + threadIdx.x;
    if (k == 0) g_loss_acc = 0.0;
    if (k < K_CODES) {
        const float* row = emb + (size_t)k * D_DIM;
        float b = 0.0f;
        #pragma unroll
        for (int i = 0; i < 16; i++) {
            float4 v = *(const float4*)(row + i * 4);
            b = __fmaf_rn(v.x, v.x, b);
            b = __fmaf_rn(v.y, v.y, b);
            b = __fmaf_rn(v.z, v.z, b);
            b = __fmaf_rn(v.w, v.w, b);
        }
        g_eB[k] = b;
    }
}

// Main kernel: one block = 128 positions of one image, all 1024 codes.
__global__ void __launch_bounds__(256, 2) vq_main(const float* __restrict__ x,
                                                  const float* __restrict__ emb,
                                                  float* __restrict__ out,
                                                  int out_size, int nblocks) {
    extern __shared__ char smem_raw[];
    float* Xs   = (float*)smem_raw;                        // [64][128]     32768 B
    float* Es   = (float*)(smem_raw + 32768);              // [2][64][132]  67584 B
    float* Bs   = (float*)(smem_raw + 32768 + 67584);      // [2][128]       1024 B
    float* As   = (float*)(smem_raw + 101376);             // [128]           512 B
    int*   idx_s = (int*)(smem_raw + 101888);              // [128]           512 B
    // reduction overlays Es buffer 0 (only used after all chunks done):
    float* rV = Es;                                        // [8][128]
    int*   rI = (int*)Es + 1024;                           // [8][128]

    const int tid = threadIdx.x;
    const int tx = tid & 31;            // position group (4 positions)
    const int ty = tid >> 5;            // code group (16 codes) — warp-uniform
    const int b  = blockIdx.x >> 3;
    const int p0 = (blockIdx.x & 7) * TP;
    const int st_dc = tid & 15;         // staging d-chunk (float4)
    const int st_s  = st_dc >> 1;       // staging swizzle const (= d>>3)
    const int krow  = tid >> 4;

    // ---- load X tile: Xs[d][pp] = x[(b*64+d)*1024 + p0 + pp] ----
    {
        const float* xb = x + (size_t)b * 65536 + p0;
        int chunk = tid & 31;           // 32 float4 per row of 128
        int r0    = tid >> 5;           // 8 rows per iter
        #pragma unroll
        for (int it = 0; it < 8; it++) {
            int d = r0 + it * 8;
            float4 v = *(const float4*)(xb + d * 1024 + chunk * 4);
            *(float4*)&Xs[d * TP + chunk * 4] = v;
        }
    }
    __syncthreads();

    // ---- A_p = sum(x^2): float2 leaves + binary tree (frozen order) ----
    if (tid < TP) {
        float l[32];
        #pragma unroll
        for (int t = 0; t < 32; t++) {
            float a = Xs[(2 * t) * TP + tid];
            float c = Xs[(2 * t + 1) * TP + tid];
            l[t] = __fmaf_rn(c, c, __fmul_rn(a, a));
        }
        #pragma unroll
        for (int off = 16; off >= 1; off >>= 1)
            #pragma unroll
            for (int t = 0; t < 16; t++)
                if (t < off) l[t] = __fadd_rn(l[t], l[t + off]);
        As[tid] = l[0];
    }
    __syncthreads();

    const ull neg2 = pk2(-2.0f, -2.0f);
    float bv[4];
    int   bi[4];
    #pragma unroll
    for (int i = 0; i < 4; i++) { bv[i] = CUDART_INF_F; bi[i] = 0; }

    // ---- K chunks: stage(c) -> sync -> compute(c); double buffer ----
    for (int kc = 0; kc < K_CODES / TK; kc++) {
        const int k0 = kc * TK;
        float* Eb = Es + (kc & 1) * EBUF;
        float* Bb = Bs + (kc & 1) * TK;

        // stage E chunk, transposed + granule-XOR swizzle:
        //   element (d, k) -> word d*EROW + (((k>>2) ^ (d>>3)) << 2) + (k&3)
        {
            #pragma unroll
            for (int it = 0; it < 8; it++) {
                int k = krow + it * 16;
                float4 v = *(const float4*)(emb + (size_t)(k0 + k) * 64 + st_dc * 4);
                int swc = ((((k >> 2) ^ st_s) << 2) + (k & 3));
                Eb[(st_dc * 4 + 0) * EROW + swc] = v.x;
                Eb[(st_dc * 4 + 1) * EROW + swc] = v.y;
                Eb[(st_dc * 4 + 2) * EROW + swc] = v.z;
                Eb[(st_dc * 4 + 3) * EROW + swc] = v.w;
            }
            if (tid < TK) Bb[tid] = g_eB[k0 + tid];
        }
        __syncthreads();

        // compute: acc[4 pos][8 pairs] (16 codes), ascending-d chains
        ull acc[4][8];
        #pragma unroll
        for (int p = 0; p < 4; p++)
            #pragma unroll
            for (int kk = 0; kk < 8; kk++) acc[p][kk] = 0ull;

        #pragma unroll
        for (int d8 = 0; d8 < 8; d8++) {
            int goff0 = (((4 * ty + 0) ^ d8) << 2);
            int goff1 = (((4 * ty + 1) ^ d8) << 2);
            int goff2 = (((4 * ty + 2) ^ d8) << 2);
            int goff3 = (((4 * ty + 3) ^ d8) << 2);
            #pragma unroll
            for (int dj = 0; dj < 8; dj++) {
                const int d = d8 * 8 + dj;
                const float* Ed = Eb + d * EROW;
                ulonglong2 e01 = *(const ulonglong2*)(Ed + goff0);
                ulonglong2 e23 = *(const ulonglong2*)(Ed + goff1);
                ulonglong2 e45 = *(const ulonglong2*)(Ed + goff2);
                ulonglong2 e67 = *(const ulonglong2*)(Ed + goff3);
                float4 xv = *(const float4*)&Xs[d * TP + tx * 4];
                ull ep[8] = { e01.x, e01.y, e23.x, e23.y,
                              e45.x, e45.y, e67.x, e67.y };
                float xs4[4] = { xv.x, xv.y, xv.z, xv.w };
                #pragma unroll
                for (int p = 0; p < 4; p++) {
                    ull xp = pk2(xs4[p], xs4[p]);
                    #pragma unroll
                    for (int kk = 0; kk < 8; kk++)
                        acc[p][kk] = ffma2(xp, ep[kk], acc[p][kk]);
                }
            }
        }

        // fold: d = fl(fl(A - 2M) + B); even code first -> lowest idx on tie
        #pragma unroll
        for (int p = 0; p < 4; p++) {
            float Ap = As[tx * 4 + p];
            ull Apk = pk2(Ap, Ap);
            #pragma unroll
            for (int kk = 0; kk < 8; kk++) {
                ull B2 = ((const ull*)Bb)[ty * 8 + kk];
                ull dpk = add2(ffma2(neg2, acc[p][kk], Apk), B2);
                float d0, d1;
                upk2(dpk, d0, d1);
                int ke = k0 + ty * 16 + 2 * kk;
                if (d0 < bv[p]) { bv[p] = d0; bi[p] = ke; }
                if (d1 < bv[p]) { bv[p] = d1; bi[p] = ke + 1; }
            }
        }
    }

    // ---- cross-thread (ty) reduction per position: min, tie -> lowest idx ----
    #pragma unroll
    for (int p = 0; p < 4; p++) {
        rV[ty * TP + tx * 4 + p] = bv[p];
        rI[ty * TP + tx * 4 + p] = bi[p];
    }
    __syncthreads();
    if (tid < TP) {
        float best = rV[tid];
        int besti  = rI[tid];
        #pragma unroll
        for (int t = 1; t < 8; t++) {
            float v = rV[t * TP + tid];
            int iv  = rI[t * TP + tid];
            if (v < best || (v == best && iv < besti)) { best = v; besti = iv; }
        }
        idx_s[tid] = besti;
        if (out_size >= TOTAL_OUT)
            out[ENC_OFF + b * 1024 + p0 + tid] = (float)besti;
    }
    __syncthreads();

    // ---- output (straight-through: x + fl(q - x)) + loss partial ----
    float lsum = 0.0f;
    #pragma unroll
    for (int j = 0; j < 32; j++) {
        int i  = tid + j * 256;
        int pp = i & 127;
        int d  = i >> 7;
        float q2 = emb[(size_t)idx_s[pp] * 64 + d];
        float xv = Xs[d * TP + pp];
        float df = __fadd_rn(q2, -xv);
        lsum += df * df;
        out[((size_t)b * 64 + d) * 1024 + p0 + pp] = __fadd_rn(xv, df);
    }
    #pragma unroll
    for (int off = 16; off > 0; off >>= 1)
        lsum += __shfl_down_sync(0xffffffffu, lsum, off);
    __shared__ float wsum[8];
    if ((tid & 31) == 0) wsum[tid >> 5] = lsum;
    __syncthreads();
    if (tid == 0) {
        float t = 0.0f;
        #pragma unroll
        for (int w = 0; w < 8; w++) t += wsum[w];
        atomicAdd(&g_loss_acc, (double)t);
        __threadfence();
        int old = atomicAdd(&g_done, 1);
        if (old == nblocks - 1) {               // last block finalizes
            g_done = 0;
            if (out_size >= TOTAL_OUT) {
                float m = (float)(g_loss_acc * (1.0 / 4194304.0));
                out[LOSS_OFF] = __fadd_rn(m, __fmul_rn(0.25f, m));
                out[NLL_OFF]  = 1.0f;
            }
        }
    }
}

extern "C" void kernel_launch(void* const* d_in, const int* in_sizes, int n_in,
                              void* d_out, int out_size) {
    const float* x   = (const float*)d_in[0];
    const float* emb = (const float*)d_in[1];
    if (n_in >= 2 && in_sizes[0] == K_CODES * D_DIM) {
        const float* t = x; x = emb; emb = t;
    }
    float* out = (float*)d_out;

    const int smem_bytes = 32768 + 67584 + 1024 + 512 + 512;   // 102400
    cudaFuncSetAttribute(vq_main, cudaFuncAttributeMaxDynamicSharedMemorySize,
                         smem_bytes);

    vq_prep<<<4, 256>>>(emb);
    vq_main<<<512, 256, smem_bytes>>>(x, emb, out, out_size, 512);
}